// round 5
// baseline (speedup 1.0000x reference)
#include <cuda_runtime.h>
#include <cuda_bf16.h>

// Problem constants (fixed by reference):
//   N = 2048 languages, D = 64 embedding dim, V = 2048 vocab
#define N_LANG 2048
#define D_EMB  64
#define V_VOC  2048
#define TI     8      // i-rows per block in the pair kernel

typedef unsigned long long ull;

// ---------------- device scratch (static: allocation-free) ----------------
__device__ float  g_combined[V_VOC * V_VOC];           // 16 MB: 0.5*(tree + map/largest)
__device__ float2 g_ETp[(D_EMB / 2) * N_LANG];         // 512 KB: packed transposed embeddings
__device__ unsigned int       g_max_bits;
__device__ double             g_sum;
__device__ unsigned long long g_cnt;

// ---------------- packed fp32x2 helper ----------------
__device__ __forceinline__ ull f32x2_add(ull a, ull b) {
    ull r;
    asm("add.rn.f32x2 %0, %1, %2;" : "=l"(r) : "l"(a), "l"(b));
    return r;
}

// ---------------- kernel 0: reset accumulators ----------------
__global__ void init_kernel() {
    g_max_bits = 0u;
    g_sum = 0.0;
    g_cnt = 0ull;
}

// ---------------- kernel 1: largest = max(map_dist) ----------------
// map values are >= 0 (avg of two uniforms), so uint-bit atomicMax is valid.
__global__ void max_kernel(const float4* __restrict__ map4) {
    int idx = blockIdx.x * blockDim.x + threadIdx.x;
    float4 v = map4[idx];
    float m = fmaxf(fmaxf(v.x, v.y), fmaxf(v.z, v.w));
#pragma unroll
    for (int o = 16; o; o >>= 1) m = fmaxf(m, __shfl_xor_sync(0xffffffffu, m, o));
    __shared__ float sm[8];
    int w = threadIdx.x >> 5;
    if ((threadIdx.x & 31) == 0) sm[w] = m;
    __syncthreads();
    if (threadIdx.x == 0) {
        float bm = sm[0];
#pragma unroll
        for (int i = 1; i < 8; i++) bm = fmaxf(bm, sm[i]);
        atomicMax(&g_max_bits, __float_as_uint(bm));
    }
}

// ---------------- kernel 2: combined = 0.5*(tree + map/largest) ----------------
__global__ void combine_kernel(const float4* __restrict__ tree4,
                               const float4* __restrict__ map4) {
    int idx = blockIdx.x * blockDim.x + threadIdx.x;
    float inv = 1.0f / __uint_as_float(g_max_bits);
    float4 t = tree4[idx];
    float4 m = map4[idx];
    float4 c;
    c.x = 0.5f * (t.x + m.x * inv);
    c.y = 0.5f * (t.y + m.y * inv);
    c.z = 0.5f * (t.z + m.z * inv);
    c.w = 0.5f * (t.w + m.w * inv);
    reinterpret_cast<float4*>(g_combined)[idx] = c;
}

// ---------------- kernel 3: transpose embeddings into packed float2 ----------------
// g_ETp[dp * N + j] = (E[j][2dp], E[j][2dp+1])
__global__ void transpose_kernel(const float* __restrict__ E) {
    int idx = blockIdx.x * blockDim.x + threadIdx.x;   // 0 .. N*D/2-1
    int dp = idx >> 11;        // / N_LANG
    int j  = idx & (N_LANG - 1);
    g_ETp[idx] = make_float2(E[j * D_EMB + 2 * dp], E[j * D_EMB + 2 * dp + 1]);
}

// ---------------- kernel 4: main pair kernel ----------------
// Block: TI=8 consecutive i-rows x all 2048 j. 256 threads = 8 warps;
// lanes along j (32 j per warp-chunk), warp strides chunks by 8.
// E_j: register-resident packed f32x2 (coalesced LDG.64 from g_ETp), reused over 8 i.
// E_i: negated, in smem, broadcast LDS.128.
// combined rows for the block's 8 ids staged in smem (gather becomes LDS).
__global__ void __launch_bounds__(256, 2)
pair_kernel(const int* __restrict__ ids) {
    extern __shared__ float smem[];
    float* s_comb  = smem;                          // TI * V floats (64 KB)
    float* s_negEi = smem + TI * V_VOC;             // TI * D floats (2 KB)
    int*   s_idi   = (int*)(s_negEi + TI * D_EMB);  // TI ints

    const int i0 = blockIdx.x * TI;
    const int tid = threadIdx.x;

    if (tid < TI) s_idi[tid] = ids[i0 + tid];
    if (tid < TI * D_EMB / 4) {
        float4 v = reinterpret_cast<const float4*>(g_ETp /*unused*/) ? make_float4(0,0,0,0) : make_float4(0,0,0,0);
        (void)v;
    }
    __syncthreads();

    // stage negated E_i rows (read original row-major E via g_ETp is transposed;
    // easier: reconstruct from ETp? No — read straight from ETp columns is strided.
    // We kept the original E pointer unnecessary; read from g_ETp transposed instead:
    // s_negEi[il*D + 2dp(+1)] = -g_ETp[dp*N + (i0+il)]
    if (tid < TI * (D_EMB / 2)) {
        int il = tid / (D_EMB / 2);
        int dp = tid % (D_EMB / 2);
        float2 v = g_ETp[dp * N_LANG + (i0 + il)];
        s_negEi[il * D_EMB + 2 * dp]     = -v.x;
        s_negEi[il * D_EMB + 2 * dp + 1] = -v.y;
    }
    __syncthreads();   // s_idi ready for combined staging

    // stage combined rows: 8 rows * 2048 floats = 4096 float4, 16 per thread
#pragma unroll
    for (int r = 0; r < 16; r++) {
        int f4  = r * 256 + tid;        // 0..4095
        int il  = f4 >> 9;              // / 512
        int col = f4 & 511;
        reinterpret_cast<float4*>(s_comb)[f4] =
            reinterpret_cast<const float4*>(g_combined)[s_idi[il] * (V_VOC / 4) + col];
    }
    __syncthreads();

    int idi[TI];
#pragma unroll
    for (int il = 0; il < TI; il++) idi[il] = s_idi[il];

    const int warp = tid >> 5;
    const int lane = tid & 31;
    float    fsum = 0.0f;
    unsigned cnt  = 0;
    const ull ABSM = 0x7FFFFFFF7FFFFFFFull;

    for (int c = warp; c < N_LANG / 32; c += 8) {
        const int j   = c * 32 + lane;
        const int idj = __ldg(&ids[j]);

        ull ej[D_EMB / 2];
#pragma unroll
        for (int dp = 0; dp < D_EMB / 2; dp++) {
            float2 v = g_ETp[dp * N_LANG + j];   // coalesced LDG.64
            union { float2 f; ull u; } cv;
            cv.f = v;
            ej[dp] = cv.u;
        }

#pragma unroll
        for (int il = 0; il < TI; il++) {
            ull a0 = 0, a1 = 0, a2 = 0, a3 = 0;
            const ulonglong2* ei =
                reinterpret_cast<const ulonglong2*>(s_negEi + il * D_EMB);
#pragma unroll
            for (int q = 0; q < D_EMB / 4; q++) {
                ulonglong2 e = ei[q];               // broadcast LDS.128
                ull d0 = f32x2_add(ej[2 * q],     e.x) & ABSM;
                ull d1 = f32x2_add(ej[2 * q + 1], e.y) & ABSM;
                if (q & 1) { a2 = f32x2_add(a2, d0); a3 = f32x2_add(a3, d1); }
                else       { a0 = f32x2_add(a0, d0); a1 = f32x2_add(a1, d1); }
            }
            a0 = f32x2_add(a0, a2);
            a1 = f32x2_add(a1, a3);
            a0 = f32x2_add(a0, a1);
            union { ull u; float2 f; } cv;
            cv.u = a0;
            float emb = (cv.f.x + cv.f.y) * (1.0f / 64.0f);
            float cm  = s_comb[il * V_VOC + idj];   // smem gather
            if (idi[il] != idj) {
                fsum += fabsf(emb - cm);
                cnt++;
            }
        }
    }

    // block reduction -> global double accumulator
#pragma unroll
    for (int o = 16; o; o >>= 1) {
        fsum += __shfl_down_sync(0xffffffffu, fsum, o);
        cnt  += __shfl_down_sync(0xffffffffu, cnt, o);
    }
    __shared__ float    rs[8];
    __shared__ unsigned rc[8];
    if (lane == 0) { rs[warp] = fsum; rc[warp] = cnt; }
    __syncthreads();
    if (tid == 0) {
        float fs = 0.0f;
        unsigned cc = 0;
#pragma unroll
        for (int w = 0; w < 8; w++) { fs += rs[w]; cc += rc[w]; }
        atomicAdd(&g_sum, (double)fs);
        atomicAdd(&g_cnt, (unsigned long long)cc);
    }
}

// ---------------- kernel 5: finalize ----------------
__global__ void finalize_kernel(float* __restrict__ out) {
    out[0] = (float)(g_sum / (double)g_cnt);
}

// ---------------- launch ----------------
extern "C" void kernel_launch(void* const* d_in, const int* in_sizes, int n_in,
                              void* d_out, int out_size) {
    // Robust input mapping by element counts:
    //   ids: 2048 (int32), emb: 131072 (f32), tree/map: 4194304 each (f32, in order)
    const int*   ids  = nullptr;
    const float* E    = nullptr;
    const float* tree = nullptr;
    const float* mapd = nullptr;
    for (int i = 0; i < n_in; i++) {
        int sz = in_sizes[i];
        if (sz == N_LANG)              ids = (const int*)d_in[i];
        else if (sz == N_LANG * D_EMB) E   = (const float*)d_in[i];
        else if (sz == V_VOC * V_VOC) {
            if (!tree) tree = (const float*)d_in[i];
            else       mapd = (const float*)d_in[i];
        }
    }
    float* out = (float*)d_out;

    const int SMEM_BYTES = (TI * V_VOC + TI * D_EMB + 16) * (int)sizeof(float);
    cudaFuncSetAttribute(pair_kernel,
                         cudaFuncAttributeMaxDynamicSharedMemorySize, SMEM_BYTES);

    init_kernel<<<1, 1>>>();
    max_kernel<<<(V_VOC * V_VOC / 4) / 256, 256>>>((const float4*)mapd);
    combine_kernel<<<(V_VOC * V_VOC / 4) / 256, 256>>>((const float4*)tree,
                                                       (const float4*)mapd);
    transpose_kernel<<<(N_LANG * D_EMB / 2) / 256, 256>>>(E);
    pair_kernel<<<N_LANG / TI, 256, SMEM_BYTES>>>(ids);
    finalize_kernel<<<1, 1>>>(out);
}